// round 8
// baseline (speedup 1.0000x reference)
#include <cuda_runtime.h>
#include <cuda_bf16.h>
#include <math.h>
#include <stdint.h>

#define NDIM 4096

// ===================== scratch (no allocation allowed) =====================
__device__ __nv_bfloat16 g_xhi[(size_t)NDIM * NDIM];
__device__ __nv_bfloat16 g_xlo[(size_t)NDIM * NDIM];
__device__ __nv_bfloat16 g_wqhi[(size_t)NDIM * NDIM];
__device__ __nv_bfloat16 g_wqlo[(size_t)NDIM * NDIM];
__device__ __nv_bfloat16 g_wkhi[(size_t)NDIM * NDIM];
__device__ __nv_bfloat16 g_wklo[(size_t)NDIM * NDIM];
__device__ __nv_bfloat16 g_wvhi[(size_t)NDIM * NDIM];
__device__ __nv_bfloat16 g_wvlo[(size_t)NDIM * NDIM];
__device__ __nv_bfloat16 g_qhi[(size_t)NDIM * NDIM];
__device__ __nv_bfloat16 g_qlo[(size_t)NDIM * NDIM];
__device__ __nv_bfloat16 g_khi[(size_t)NDIM * NDIM];
__device__ __nv_bfloat16 g_klo[(size_t)NDIM * NDIM];
__device__ float         g_v  [(size_t)NDIM * NDIM];

// ===================== small PTX helpers =====================
__device__ __forceinline__ uint32_t smem_u32(const void* p) {
    uint32_t a;
    asm("{ .reg .u64 t; cvta.to.shared.u64 t, %1; cvt.u32.u64 %0, t; }" : "=r"(a) : "l"(p));
    return a;
}
__device__ __forceinline__ void cp16(uint32_t s, const void* g) {
    asm volatile("cp.async.cg.shared.global [%0], [%1], 16;" :: "r"(s), "l"(g));
}
#define CP_COMMIT() asm volatile("cp.async.commit_group;" ::: "memory")
#define CP_WAIT(n)  asm volatile("cp.async.wait_group %0;" :: "n"(n) : "memory")

__device__ __forceinline__ void ldsm4(uint32_t* r, uint32_t addr) {
    asm volatile("ldmatrix.sync.aligned.m8n8.x4.shared.b16 {%0,%1,%2,%3}, [%4];"
        : "=r"(r[0]), "=r"(r[1]), "=r"(r[2]), "=r"(r[3]) : "r"(addr));
}
__device__ __forceinline__ void mma16816(float* c, const uint32_t* a, uint32_t b0, uint32_t b1) {
    asm volatile("mma.sync.aligned.m16n8k16.row.col.f32.bf16.bf16.f32 "
        "{%0,%1,%2,%3},{%4,%5,%6,%7},{%8,%9},{%0,%1,%2,%3};"
        : "+f"(c[0]), "+f"(c[1]), "+f"(c[2]), "+f"(c[3])
        : "r"(a[0]), "r"(a[1]), "r"(a[2]), "r"(a[3]), "r"(b0), "r"(b1));
}

// Tile rows are 64B (4 x 16B chunks); chunk permuted by (row>>1)&3.
__device__ __forceinline__ uint32_t sw_addr(uint32_t tile_base, int row, int c) {
    return tile_base + row * 64 + ((c ^ ((row >> 1) & 3)) << 4);
}

// ===================== merged fp32 -> bf16 hi/lo split (z selects tensor) ===
__global__ void __launch_bounds__(256)
split_hi_lo4(const float* __restrict__ i0, __nv_bfloat16* __restrict__ h0p, __nv_bfloat16* __restrict__ l0p,
             const float* __restrict__ i1, __nv_bfloat16* __restrict__ h1p, __nv_bfloat16* __restrict__ l1p,
             const float* __restrict__ i2, __nv_bfloat16* __restrict__ h2p, __nv_bfloat16* __restrict__ l2p,
             const float* __restrict__ i3, __nv_bfloat16* __restrict__ h3p, __nv_bfloat16* __restrict__ l3p)
{
    const float* in;
    __nv_bfloat16 *hi, *lo;
    switch (blockIdx.z) {
        case 0: in = i0; hi = h0p; lo = l0p; break;
        case 1: in = i1; hi = h1p; lo = l1p; break;
        case 2: in = i2; hi = h2p; lo = l2p; break;
        default: in = i3; hi = h3p; lo = l3p; break;
    }
    size_t i = ((size_t)blockIdx.x * 256 + threadIdx.x) * 4;
    float4 v = *(const float4*)(in + i);
    __nv_bfloat16 a0 = __float2bfloat16(v.x), a1 = __float2bfloat16(v.y);
    __nv_bfloat16 a2 = __float2bfloat16(v.z), a3 = __float2bfloat16(v.w);
    __nv_bfloat16 b0 = __float2bfloat16(v.x - __bfloat162float(a0));
    __nv_bfloat16 b1 = __float2bfloat16(v.y - __bfloat162float(a1));
    __nv_bfloat16 b2 = __float2bfloat16(v.z - __bfloat162float(a2));
    __nv_bfloat16 b3 = __float2bfloat16(v.w - __bfloat162float(a3));
    *(__nv_bfloat162*)(hi + i)     = __halves2bfloat162(a0, a1);
    *(__nv_bfloat162*)(hi + i + 2) = __halves2bfloat162(a2, a3);
    *(__nv_bfloat162*)(lo + i)     = __halves2bfloat162(b0, b1);
    *(__nv_bfloat162*)(lo + i + 2) = __halves2bfloat162(b2, b3);
}

// ===================== HMMA mainloop (shared) =====================
#define NSTAGE 3
#define STAGE_B 32768
#define OFF_AHI 0
#define OFF_ALO 8192
#define OFF_BHI 16384
#define OFF_BLO 24576
#define DYN_SMEM (NSTAGE * STAGE_B)

__device__ __forceinline__ void load_stage(
    uint32_t sb, int stage, int k0, int m0, int n0, int tid,
    const __nv_bfloat16* __restrict__ Ahi, const __nv_bfloat16* __restrict__ Alo,
    const __nv_bfloat16* __restrict__ Bhi, const __nv_bfloat16* __restrict__ Blo)
{
    const uint32_t st = sb + stage * STAGE_B;
#pragma unroll
    for (int i = 0; i < 2; i++) {
        const int slot = tid + i * 256;        // 0..511
        const int r = slot >> 2;               // 0..127
        const int c = slot & 3;                // 16B chunk in 64B row
        const uint32_t sw = sw_addr(0, r, c);
        const size_t ga = (size_t)(m0 + r) * NDIM + k0 + c * 8;
        const size_t gb = (size_t)(n0 + r) * NDIM + k0 + c * 8;
        cp16(st + OFF_AHI + sw, Ahi + ga);
        cp16(st + OFF_ALO + sw, Alo + ga);
        cp16(st + OFF_BHI + sw, Bhi + gb);
        cp16(st + OFF_BLO + sw, Blo + gb);
    }
}

// acc layout: acc[4][4][4]  (mt, nt, frag)
__device__ __forceinline__ void mainloop(
    uint32_t sb, int tid, int m0, int n0,
    const __nv_bfloat16* __restrict__ Ahi, const __nv_bfloat16* __restrict__ Alo,
    const __nv_bfloat16* __restrict__ Bhi, const __nv_bfloat16* __restrict__ Blo,
    float acc[4][4][4])
{
    const int lane = tid & 31;
    const int w    = tid >> 5;
    const int wm0  = (w & 1) * 64;
    const int wn0  = (w >> 1) * 32;
    const int arow  = (lane & 15);
    const int ahalf = (lane >> 4);

#pragma unroll
    for (int s = 0; s < NSTAGE - 1; s++) {
        load_stage(sb, s, s * 32, m0, n0, tid, Ahi, Alo, Bhi, Blo);
        CP_COMMIT();
    }

    for (int i = 0; i < NDIM / 32; i++) {
        CP_WAIT(1);
        __syncthreads();
        const int j = i + NSTAGE - 1;
        if (j < NDIM / 32)
            load_stage(sb, j % NSTAGE, j * 32, m0, n0, tid, Ahi, Alo, Bhi, Blo);
        CP_COMMIT();

        const uint32_t st = sb + (i % NSTAGE) * STAGE_B;
#pragma unroll
        for (int ks = 0; ks < 2; ks++) {
            const int c = ks * 2 + ahalf;
            uint32_t bh[2][4], bl[2][4];
#pragma unroll
            for (int p = 0; p < 2; p++) {
                const int r = wn0 + p * 16 + arow;
                ldsm4(bh[p], sw_addr(st + OFF_BHI, r, c));
                ldsm4(bl[p], sw_addr(st + OFF_BLO, r, c));
            }
#pragma unroll
            for (int mt = 0; mt < 4; mt++) {
                const int r = wm0 + mt * 16 + arow;
                uint32_t ah[4], al[4];
                ldsm4(ah, sw_addr(st + OFF_AHI, r, c));
                ldsm4(al, sw_addr(st + OFF_ALO, r, c));
                // hh group (4 independent accs)
                mma16816(acc[mt][0], ah, bh[0][0], bh[0][2]);
                mma16816(acc[mt][1], ah, bh[0][1], bh[0][3]);
                mma16816(acc[mt][2], ah, bh[1][0], bh[1][2]);
                mma16816(acc[mt][3], ah, bh[1][1], bh[1][3]);
                // lh group
                mma16816(acc[mt][0], al, bh[0][0], bh[0][2]);
                mma16816(acc[mt][1], al, bh[0][1], bh[0][3]);
                mma16816(acc[mt][2], al, bh[1][0], bh[1][2]);
                mma16816(acc[mt][3], al, bh[1][1], bh[1][3]);
                // hl group
                mma16816(acc[mt][0], ah, bl[0][0], bl[0][2]);
                mma16816(acc[mt][1], ah, bl[0][1], bl[0][3]);
                mma16816(acc[mt][2], ah, bl[1][0], bl[1][2]);
                mma16816(acc[mt][3], ah, bl[1][1], bl[1][3]);
            }
        }
    }
}

// ===================== merged q/k/v projection GEMM (grid.z selects) =======
__global__ void __launch_bounds__(256, 2)
proj_gemm(const __nv_bfloat16* __restrict__ xhi, const __nv_bfloat16* __restrict__ xlo,
          const __nv_bfloat16* __restrict__ wqhi, const __nv_bfloat16* __restrict__ wqlo,
          const __nv_bfloat16* __restrict__ wkhi, const __nv_bfloat16* __restrict__ wklo,
          const __nv_bfloat16* __restrict__ wvhi, const __nv_bfloat16* __restrict__ wvlo,
          const float* __restrict__ bq, const float* __restrict__ bk, const float* __restrict__ bv,
          __nv_bfloat16* __restrict__ qhi, __nv_bfloat16* __restrict__ qlo,
          __nv_bfloat16* __restrict__ khi, __nv_bfloat16* __restrict__ klo,
          float* __restrict__ vp)
{
    extern __shared__ char dynsmem[];
    const uint32_t sb = smem_u32(dynsmem);
    const int tid = threadIdx.x;
    const int m0 = blockIdx.y * 128;
    const int n0 = blockIdx.x * 128;
    const int z  = blockIdx.z;

    const __nv_bfloat16 *Bhi, *Blo;
    const float* bias;
    if (z == 0)      { Bhi = wqhi; Blo = wqlo; bias = bq; }
    else if (z == 1) { Bhi = wkhi; Blo = wklo; bias = bk; }
    else             { Bhi = wvhi; Blo = wvlo; bias = bv; }

    float acc[4][4][4];
#pragma unroll
    for (int mt = 0; mt < 4; mt++)
#pragma unroll
        for (int nt = 0; nt < 4; nt++)
#pragma unroll
            for (int e = 0; e < 4; e++) acc[mt][nt][e] = 0.0f;

    mainloop(sb, tid, m0, n0, xhi, xlo, Bhi, Blo, acc);

    const int lane = tid & 31;
    const int w    = tid >> 5;
    const int wm0  = (w & 1) * 64;
    const int wn0  = (w >> 1) * 32;
#pragma unroll
    for (int mt = 0; mt < 4; mt++) {
#pragma unroll
        for (int nt = 0; nt < 4; nt++) {
            const int r0  = m0 + wm0 + mt * 16 + (lane >> 2);
            const int col = n0 + wn0 + nt * 8 + (lane & 3) * 2;
            const float* cc = acc[mt][nt];
#pragma unroll
            for (int h = 0; h < 2; h++) {
                const int r = r0 + h * 8;
                float f0 = cc[2 * h + 0] + __ldg(&bias[col]);
                float f1 = cc[2 * h + 1] + __ldg(&bias[col + 1]);
                if (z == 2) {
                    *(float2*)&vp[(size_t)r * NDIM + col] = make_float2(f0, f1);
                } else {
                    __nv_bfloat16 h0 = __float2bfloat16(f0), h1 = __float2bfloat16(f1);
                    __nv_bfloat16 l0 = __float2bfloat16(f0 - __bfloat162float(h0));
                    __nv_bfloat16 l1 = __float2bfloat16(f1 - __bfloat162float(h1));
                    __nv_bfloat16* dh = (z == 0) ? qhi : khi;
                    __nv_bfloat16* dl = (z == 0) ? qlo : klo;
                    *(__nv_bfloat162*)&dh[(size_t)r * NDIM + col] = __halves2bfloat162(h0, h1);
                    *(__nv_bfloat162*)&dl[(size_t)r * NDIM + col] = __halves2bfloat162(l0, l1);
                }
            }
        }
    }
}

// ===================== attention logits GEMM: S = (q @ k^T) * alpha ========
__global__ void __launch_bounds__(256, 2)
attn_gemm(const __nv_bfloat16* __restrict__ Ahi, const __nv_bfloat16* __restrict__ Alo,
          const __nv_bfloat16* __restrict__ Bhi, const __nv_bfloat16* __restrict__ Blo,
          float alpha, float* __restrict__ Cf)
{
    extern __shared__ char dynsmem[];
    const uint32_t sb = smem_u32(dynsmem);
    const int tid = threadIdx.x;
    const int m0 = blockIdx.y * 128;
    const int n0 = blockIdx.x * 128;

    float acc[4][4][4];
#pragma unroll
    for (int mt = 0; mt < 4; mt++)
#pragma unroll
        for (int nt = 0; nt < 4; nt++)
#pragma unroll
            for (int e = 0; e < 4; e++) acc[mt][nt][e] = 0.0f;

    mainloop(sb, tid, m0, n0, Ahi, Alo, Bhi, Blo, acc);

    const int lane = tid & 31;
    const int w    = tid >> 5;
    const int wm0  = (w & 1) * 64;
    const int wn0  = (w >> 1) * 32;
#pragma unroll
    for (int mt = 0; mt < 4; mt++) {
#pragma unroll
        for (int nt = 0; nt < 4; nt++) {
            const int r0  = m0 + wm0 + mt * 16 + (lane >> 2);
            const int col = n0 + wn0 + nt * 8 + (lane & 3) * 2;
            const float* cc = acc[mt][nt];
#pragma unroll
            for (int h = 0; h < 2; h++) {
                const int r = r0 + h * 8;
                *(float2*)&Cf[(size_t)r * NDIM + col] =
                    make_float2(cc[2 * h] * alpha, cc[2 * h + 1] * alpha);
            }
        }
    }
}

// ===================== softmax(S) * v, in place on d_out =====================
__global__ void __launch_bounds__(256)
softmax_mul(const float* __restrict__ S, const float* __restrict__ V, float* __restrict__ out)
{
    __shared__ float red[256];
    const int row = blockIdx.x;
    const int tid = threadIdx.x;
    const float* s = S + (size_t)row * NDIM;

    float vals[16];
    float m = -INFINITY;
#pragma unroll
    for (int i = 0; i < 16; i++) {
        vals[i] = s[tid + i * 256];
        m = fmaxf(m, vals[i]);
    }
    red[tid] = m;
    __syncthreads();
#pragma unroll
    for (int w = 128; w > 0; w >>= 1) {
        if (tid < w) red[tid] = fmaxf(red[tid], red[tid + w]);
        __syncthreads();
    }
    m = red[0];
    __syncthreads();

    float sum = 0.0f;
#pragma unroll
    for (int i = 0; i < 16; i++) {
        vals[i] = expf(vals[i] - m);
        sum += vals[i];
    }
    red[tid] = sum;
    __syncthreads();
#pragma unroll
    for (int w = 128; w > 0; w >>= 1) {
        if (tid < w) red[tid] += red[tid + w];
        __syncthreads();
    }
    const float inv = 1.0f / red[0];

    const float* v = V + (size_t)row * NDIM;
    float* o = out + (size_t)row * NDIM;
#pragma unroll
    for (int i = 0; i < 16; i++) {
        const int c = tid + i * 256;
        o[c] = vals[i] * inv * v[c];
    }
}

// ===================== launch =====================
extern "C" void kernel_launch(void* const* d_in, const int* in_sizes, int n_in,
                              void* d_out, int out_size)
{
    const float* x  = (const float*)d_in[0];
    const float* Wq = (const float*)d_in[1];
    const float* bq = (const float*)d_in[2];
    const float* Wk = (const float*)d_in[3];
    const float* bk = (const float*)d_in[4];
    const float* Wv = (const float*)d_in[5];
    const float* bv = (const float*)d_in[6];
    float* out = (float*)d_out;

    __nv_bfloat16 *xhi, *xlo, *wqhi, *wqlo, *wkhi, *wklo, *wvhi, *wvlo;
    __nv_bfloat16 *qhi, *qlo, *khi, *klo;
    float* vp;
    cudaGetSymbolAddress((void**)&xhi,  g_xhi);
    cudaGetSymbolAddress((void**)&xlo,  g_xlo);
    cudaGetSymbolAddress((void**)&wqhi, g_wqhi);
    cudaGetSymbolAddress((void**)&wqlo, g_wqlo);
    cudaGetSymbolAddress((void**)&wkhi, g_wkhi);
    cudaGetSymbolAddress((void**)&wklo, g_wklo);
    cudaGetSymbolAddress((void**)&wvhi, g_wvhi);
    cudaGetSymbolAddress((void**)&wvlo, g_wvlo);
    cudaGetSymbolAddress((void**)&qhi,  g_qhi);
    cudaGetSymbolAddress((void**)&qlo,  g_qlo);
    cudaGetSymbolAddress((void**)&khi,  g_khi);
    cudaGetSymbolAddress((void**)&klo,  g_klo);
    cudaGetSymbolAddress((void**)&vp,   g_v);

    cudaFuncSetAttribute(proj_gemm, cudaFuncAttributeMaxDynamicSharedMemorySize, DYN_SMEM);
    cudaFuncSetAttribute(attn_gemm, cudaFuncAttributeMaxDynamicSharedMemorySize, DYN_SMEM);

    const int nsplit = (NDIM * NDIM) / (256 * 4);  // 16384 blocks per tensor

    // Launch 0: all four hi/lo splits (z selects tensor)
    split_hi_lo4<<<dim3(nsplit, 1, 4), 256>>>(
        x, xhi, xlo, Wq, wqhi, wqlo, Wk, wkhi, wklo, Wv, wvhi, wvlo);

    // Launch 1: merged q/k/v projections (z = 0/1/2)
    proj_gemm<<<dim3(NDIM / 128, NDIM / 128, 3), 256, DYN_SMEM>>>(
        xhi, xlo, wqhi, wqlo, wkhi, wklo, wvhi, wvlo,
        bq, bk, bv, qhi, qlo, khi, klo, vp);

    // Launch 2: S = (q @ k^T) / 64 -> d_out
    attn_gemm<<<dim3(NDIM / 128, NDIM / 128), 256, DYN_SMEM>>>(
        qhi, qlo, khi, klo, 1.0f / 64.0f, out);

    // Launch 3: out = softmax(S) * v (in place)
    softmax_mul<<<NDIM, 256>>>(out, vp, out);
}